// round 1
// baseline (speedup 1.0000x reference)
#include <cuda_runtime.h>
#include <math.h>

// Problem-shape maxima (known from the dataset; runtime values derived from in_sizes)
#define NMAX 100000
#define EMAX 1600000
#define HD   128
#define GMAXC 256

// ---------------- scratch (device globals; no allocation allowed) ----------------
__device__ int   g_cnt[NMAX];
__device__ int   g_fill[NMAX];
__device__ int   g_rowptr[NMAX + 1];
__device__ int   g_colidx[EMAX];
__device__ float g_dinv[NMAX];
__device__ float g_bufA[NMAX * HD];   // 51.2 MB
__device__ float g_bufB[NMAX * HD];   // 51.2 MB
__device__ float g_pool[GMAXC * HD];
__device__ int   g_gptr[GMAXC + 1];
__device__ int   g_bsum[256];
__device__ int   g_is64_edge;
__device__ int   g_is64_batch;

// ---------------- helpers ----------------
__device__ __forceinline__ int idx_at(const void* p, long long i, int is64) {
    return is64 ? (int)((const long long*)p)[i] : ((const int*)p)[i];
}

// Detect whether index buffers are int64 or int32.
// edge: probe first 128 words as int64 — if data is really int32, the high half of
// each word is a random node id (>=2^32 as int64) with overwhelming probability.
// batch: probe the TAIL (sorted graph ids start at 0, tail ids are ~G-1 != 0).
__global__ void k_detect(const void* edge, const void* batch, int E, int N) {
    __shared__ int ok_e, ok_b;
    if (threadIdx.x == 0) { ok_e = 1; ok_b = 1; }
    __syncthreads();
    if (threadIdx.x < 128) {
        long long v = ((const long long*)edge)[threadIdx.x];
        if (v < 0 || v >= (1LL << 31)) ok_e = 0;
    }
    int nw = N / 2;                 // safe word count under either interpretation
    int base = nw > 128 ? nw - 128 : 0;
    if (threadIdx.x < 128 && base + threadIdx.x < nw) {
        long long v = ((const long long*)batch)[base + threadIdx.x];
        if (v < 0 || v >= (1LL << 31)) ok_b = 0;
    }
    __syncthreads();
    if (threadIdx.x == 0) { g_is64_edge = ok_e; g_is64_batch = ok_b; }
}

__global__ void k_zero(int N) {
    int i = blockIdx.x * blockDim.x + threadIdx.x;
    if (i < N) { g_cnt[i] = 0; g_fill[i] = 0; }
}

__global__ void k_hist(const void* edge, int E) {
    int e = blockIdx.x * blockDim.x + threadIdx.x;
    if (e >= E) return;
    int is64 = g_is64_edge;
    int d = idx_at(edge, (long long)E + e, is64);   // dst row
    atomicAdd(&g_cnt[d], 1);
}

// 3-phase exclusive scan of g_cnt -> g_rowptr
__global__ void k_scan1(int N) {
    __shared__ int sm[1024];
    int i = blockIdx.x * 1024 + threadIdx.x;
    int v = (i < N) ? g_cnt[i] : 0;
    sm[threadIdx.x] = v;
    __syncthreads();
    for (int off = 1; off < 1024; off <<= 1) {
        int t = (threadIdx.x >= off) ? sm[threadIdx.x - off] : 0;
        __syncthreads();
        sm[threadIdx.x] += t;
        __syncthreads();
    }
    if (i < N) g_rowptr[i + 1] = sm[threadIdx.x];
    if (threadIdx.x == 1023) g_bsum[blockIdx.x] = sm[1023];
}
__global__ void k_scan2(int nb) {
    __shared__ int sm[1024];
    int v = (threadIdx.x < nb) ? g_bsum[threadIdx.x] : 0;
    sm[threadIdx.x] = v;
    __syncthreads();
    for (int off = 1; off < 1024; off <<= 1) {
        int t = (threadIdx.x >= off) ? sm[threadIdx.x - off] : 0;
        __syncthreads();
        sm[threadIdx.x] += t;
        __syncthreads();
    }
    if (threadIdx.x < nb) g_bsum[threadIdx.x] = sm[threadIdx.x] - v;  // exclusive
}
__global__ void k_scan3(int N) {
    int i = blockIdx.x * 1024 + threadIdx.x;
    if (i < N) g_rowptr[i + 1] += g_bsum[blockIdx.x];
    if (i == 0) g_rowptr[0] = 0;
}

__global__ void k_dinv(int N) {
    int i = blockIdx.x * blockDim.x + threadIdx.x;
    if (i < N) g_dinv[i] = rsqrtf((float)(g_cnt[i] + 1));  // +1 self-loop
}

__global__ void k_scatter(const void* edge, int E) {
    int e = blockIdx.x * blockDim.x + threadIdx.x;
    if (e >= E) return;
    int is64 = g_is64_edge;
    int s = idx_at(edge, e, is64);
    int d = idx_at(edge, (long long)E + e, is64);
    int pos = atomicAdd(&g_fill[d], 1);
    g_colidx[g_rowptr[d] + pos] = s;
}

// ---------------- SGEMM: out(g_bufB) = A[Nrows,128] @ W[128,128] ----------------
// 128x128 tile, BK=16, 256 threads, 8x8 register micro-tile.
__global__ void __launch_bounds__(256, 2) k_gemm(const float* __restrict__ Xext,
                                                 const float* __restrict__ W,
                                                 int useExt, int Nrows) {
    const float* A = useExt ? Xext : g_bufA;
    __shared__ float As[16][HD + 1];   // transposed, padded
    __shared__ float Bs[16][HD];
    int tid = threadIdx.x;
    int m0 = blockIdx.x * 128;
    int tx = tid & 15, ty = tid >> 4;
    float acc[8][8];
#pragma unroll
    for (int i = 0; i < 8; i++)
#pragma unroll
        for (int j = 0; j < 8; j++) acc[i][j] = 0.f;

    for (int k0 = 0; k0 < HD; k0 += 16) {
        // load A tile 128x16 (float4), store transposed
#pragma unroll
        for (int q = tid; q < 512; q += 256) {
            int row = q >> 2, kk = (q & 3) * 4;
            float4 v = make_float4(0.f, 0.f, 0.f, 0.f);
            if (m0 + row < Nrows)
                v = *(const float4*)&A[(m0 + row) * HD + k0 + kk];
            As[kk + 0][row] = v.x; As[kk + 1][row] = v.y;
            As[kk + 2][row] = v.z; As[kk + 3][row] = v.w;
        }
        // load B tile 16x128 (float4), direct
#pragma unroll
        for (int q = tid; q < 512; q += 256) {
            int kk = q >> 5, nn = (q & 31) * 4;
            *(float4*)&Bs[kk][nn] = *(const float4*)&W[(k0 + kk) * HD + nn];
        }
        __syncthreads();
#pragma unroll
        for (int kk = 0; kk < 16; kk++) {
            float a[8], b[8];
#pragma unroll
            for (int i = 0; i < 8; i++) a[i] = As[kk][ty * 8 + i];
#pragma unroll
            for (int j = 0; j < 8; j++) b[j] = Bs[kk][tx * 8 + j];
#pragma unroll
            for (int i = 0; i < 8; i++)
#pragma unroll
                for (int j = 0; j < 8; j++) acc[i][j] += a[i] * b[j];
        }
        __syncthreads();
    }
#pragma unroll
    for (int i = 0; i < 8; i++) {
        int row = m0 + ty * 8 + i;
        if (row < Nrows) {
#pragma unroll
            for (int j = 0; j < 8; j += 4) {
                float4 v = make_float4(acc[i][j], acc[i][j + 1], acc[i][j + 2], acc[i][j + 3]);
                *(float4*)&g_bufB[row * HD + tx * 8 + j] = v;
            }
        }
    }
}

// ---------------- fused aggregation + bias + ReLU ----------------
// one block (128 threads = one feature each) per dst node; CSR neighbor loop.
__global__ void k_agg(const float* __restrict__ bias, int Nrows) {
    int row = blockIdx.x;
    int f = threadIdx.x;
    float di = g_dinv[row];
    float acc = di * di * g_bufB[row * HD + f];   // self-loop
    int beg = g_rowptr[row], end = g_rowptr[row + 1];
    int e = beg;
    for (; e + 4 <= end; e += 4) {
        int s0 = g_colidx[e], s1 = g_colidx[e + 1], s2 = g_colidx[e + 2], s3 = g_colidx[e + 3];
        float w0 = g_dinv[s0], w1 = g_dinv[s1], w2 = g_dinv[s2], w3 = g_dinv[s3];
        float v0 = g_bufB[s0 * HD + f], v1 = g_bufB[s1 * HD + f];
        float v2 = g_bufB[s2 * HD + f], v3 = g_bufB[s3 * HD + f];
        acc += di * (w0 * v0 + w1 * v1 + w2 * v2 + w3 * v3);
    }
    for (; e < end; e++) {
        int s = g_colidx[e];
        acc += di * g_dinv[s] * g_bufB[s * HD + f];
    }
    acc += bias[f];
    g_bufA[row * HD + f] = fmaxf(acc, 0.f);
}

// ---------------- graph boundaries via binary search (batch is sorted) ----------------
__global__ void k_gptr(const void* batch, int N, int G) {
    int t = blockIdx.x * blockDim.x + threadIdx.x;
    if (t > G) return;
    int is64 = g_is64_batch;
    int lo = 0, hi = N;
    while (lo < hi) {
        int mid = (lo + hi) >> 1;
        if (idx_at(batch, mid, is64) < t) lo = mid + 1; else hi = mid;
    }
    g_gptr[t] = lo;
}

__global__ void k_pool() {
    int g = blockIdx.x, f = threadIdx.x;
    int beg = g_gptr[g], end = g_gptr[g + 1];
    float s = 0.f;
    int n = beg;
    for (; n + 4 <= end; n += 4) {
        s += g_bufA[n * HD + f] + g_bufA[(n + 1) * HD + f]
           + g_bufA[(n + 2) * HD + f] + g_bufA[(n + 3) * HD + f];
    }
    for (; n < end; n++) s += g_bufA[n * HD + f];
    float c = (float)(end - beg);
    g_pool[g * HD + f] = s / fmaxf(c, 1.f);
}

// ---------------- head: relu(pool@W1+b1)@W2+b2, log_softmax ----------------
__global__ void k_head(const float* __restrict__ w1, const float* __restrict__ b1,
                       const float* __restrict__ w2, const float* __restrict__ b2,
                       float* __restrict__ out, int C) {
    int g = blockIdx.x, t = threadIdx.x;
    __shared__ float row[HD];
    __shared__ float h1[HD];
    __shared__ float lg[32];
    __shared__ float s_m, s_l;
    row[t] = g_pool[g * HD + t];
    __syncthreads();
    float s = b1[t];
#pragma unroll 8
    for (int k = 0; k < HD; k++) s += row[k] * w1[k * HD + t];
    h1[t] = fmaxf(s, 0.f);
    __syncthreads();
    if (t < C) {
        float s2 = b2[t];
        for (int k = 0; k < HD; k++) s2 += h1[k] * w2[k * C + t];
        lg[t] = s2;
    }
    __syncthreads();
    if (t == 0) {
        float m = -1e30f;
        for (int c = 0; c < C; c++) m = fmaxf(m, lg[c]);
        float se = 0.f;
        for (int c = 0; c < C; c++) se += expf(lg[c] - m);
        s_m = m; s_l = logf(se);
    }
    __syncthreads();
    if (t < C) out[g * C + t] = lg[t] - s_m - s_l;
}

// ---------------- launch ----------------
extern "C" void kernel_launch(void* const* d_in, const int* in_sizes, int n_in,
                              void* d_out, int out_size) {
    const float* x      = (const float*)d_in[0];
    const void*  edge   = d_in[1];
    const void*  batch  = d_in[2];
    const float* w_init = (const float*)d_in[3];
    const float* b_init = (const float*)d_in[4];
    const float* w_conv = (const float*)d_in[5];
    const float* b_conv = (const float*)d_in[6];
    const float* w_h1   = (const float*)d_in[7];
    const float* b_h1   = (const float*)d_in[8];
    const float* w_h2   = (const float*)d_in[9];
    const float* b_h2   = (const float*)d_in[10];

    int H   = in_sizes[4];            // 128
    int N   = in_sizes[0] / H;
    int E   = in_sizes[1] / 2;
    int C   = in_sizes[10];
    int Lm1 = in_sizes[6] / H;
    int G   = out_size / C;

    int tb = 256;
    int nbN = (N + tb - 1) / tb;
    int nbE = (E + tb - 1) / tb;
    int nbS = (N + 1023) / 1024;

    k_detect<<<1, 256>>>(edge, batch, E, N);
    k_zero<<<nbN, tb>>>(N);
    k_hist<<<nbE, tb>>>(edge, E);
    k_scan1<<<nbS, 1024>>>(N);
    k_scan2<<<1, 1024>>>(nbS);
    k_scan3<<<nbS, 1024>>>(N);
    k_dinv<<<nbN, tb>>>(N);
    k_scatter<<<nbE, tb>>>(edge, E);

    int gemmBlocks = (N + 127) / 128;
    // layer 1: x @ w_init -> bufB; aggregate -> bufA
    k_gemm<<<gemmBlocks, 256>>>(x, w_init, 1, N);
    k_agg<<<N, 128>>>(b_init, N);
    // layers 2..L
    for (int i = 0; i < Lm1; i++) {
        k_gemm<<<gemmBlocks, 256>>>(x, w_conv + (size_t)i * H * H, 0, N);
        k_agg<<<N, 128>>>(b_conv + (size_t)i * H, N);
    }

    k_gptr<<<1, 256>>>(batch, N, G);
    k_pool<<<G, 128>>>();
    k_head<<<G, 128>>>(w_h1, b_h1, w_h2, b_h2, (float*)d_out, C);
}

// round 6
// speedup vs baseline: 1.0908x; 1.0908x over previous
#include <cuda_runtime.h>
#include <mma.h>
#include <math.h>

using namespace nvcuda;

// Problem-shape maxima
#define NMAX 100000
#define NPAD 100096          // 782 * 128, padded so GEMM tiles need no store guards
#define EMAX 1600000
#define HD   128
#define GMAXC 256

// ---------------- scratch (device globals; no allocation allowed) ----------------
__device__ int   g_cnt[NMAX];
__device__ int   g_fill[NMAX];
__device__ int   g_rowptr[NMAX + 1];
__device__ int   g_colidx[EMAX];
__device__ float g_dinv[NMAX];
__device__ float g_bufA[NPAD * HD];   // padded rows [N, NPAD) stay zero (never written)
__device__ float g_bufB[NPAD * HD];
__device__ float g_pool[GMAXC * HD];
__device__ int   g_gptr[GMAXC + 1];
__device__ int   g_bsum[256];
__device__ int   g_is64_edge;
__device__ int   g_is64_batch;

// ---------------- helpers ----------------
__device__ __forceinline__ int idx_at(const void* p, long long i, int is64) {
    return is64 ? (int)((const long long*)p)[i] : ((const int*)p)[i];
}

// Detect whether index buffers are int64 or int32 (JAX may emit either).
__global__ void k_detect(const void* edge, const void* batch, int E, int N) {
    __shared__ int ok_e, ok_b;
    if (threadIdx.x == 0) { ok_e = 1; ok_b = 1; }
    __syncthreads();
    if (threadIdx.x < 128) {
        long long v = ((const long long*)edge)[threadIdx.x];
        if (v < 0 || v >= (1LL << 31)) ok_e = 0;
    }
    int nw = N / 2;
    int base = nw > 128 ? nw - 128 : 0;
    if (threadIdx.x < 128 && base + threadIdx.x < nw) {
        long long v = ((const long long*)batch)[base + threadIdx.x];
        if (v < 0 || v >= (1LL << 31)) ok_b = 0;
    }
    __syncthreads();
    if (threadIdx.x == 0) { g_is64_edge = ok_e; g_is64_batch = ok_b; }
}

__global__ void k_zero(int N) {
    int i = blockIdx.x * blockDim.x + threadIdx.x;
    if (i < N) { g_cnt[i] = 0; g_fill[i] = 0; }
}

__global__ void k_hist(const void* edge, int E) {
    int e = blockIdx.x * blockDim.x + threadIdx.x;
    if (e >= E) return;
    int d = idx_at(edge, (long long)E + e, g_is64_edge);
    atomicAdd(&g_cnt[d], 1);
}

// 3-phase exclusive scan of g_cnt -> g_rowptr
__global__ void k_scan1(int N) {
    __shared__ int sm[1024];
    int i = blockIdx.x * 1024 + threadIdx.x;
    int v = (i < N) ? g_cnt[i] : 0;
    sm[threadIdx.x] = v;
    __syncthreads();
    for (int off = 1; off < 1024; off <<= 1) {
        int t = (threadIdx.x >= off) ? sm[threadIdx.x - off] : 0;
        __syncthreads();
        sm[threadIdx.x] += t;
        __syncthreads();
    }
    if (i < N) g_rowptr[i + 1] = sm[threadIdx.x];
    if (threadIdx.x == 1023) g_bsum[blockIdx.x] = sm[1023];
}
__global__ void k_scan2(int nb) {
    __shared__ int sm[1024];
    int v = (threadIdx.x < nb) ? g_bsum[threadIdx.x] : 0;
    sm[threadIdx.x] = v;
    __syncthreads();
    for (int off = 1; off < 1024; off <<= 1) {
        int t = (threadIdx.x >= off) ? sm[threadIdx.x - off] : 0;
        __syncthreads();
        sm[threadIdx.x] += t;
        __syncthreads();
    }
    if (threadIdx.x < nb) g_bsum[threadIdx.x] = sm[threadIdx.x] - v;
}
__global__ void k_scan3(int N) {
    int i = blockIdx.x * 1024 + threadIdx.x;
    if (i < N) g_rowptr[i + 1] += g_bsum[blockIdx.x];
    if (i == 0) g_rowptr[0] = 0;
}

__global__ void k_dinv(int N) {
    int i = blockIdx.x * blockDim.x + threadIdx.x;
    if (i < N) g_dinv[i] = rsqrtf((float)(g_cnt[i] + 1));
}

__global__ void k_scatter(const void* edge, int E) {
    int e = blockIdx.x * blockDim.x + threadIdx.x;
    if (e >= E) return;
    int is64 = g_is64_edge;
    int s = idx_at(edge, e, is64);
    int d = idx_at(edge, (long long)E + e, is64);
    int pos = atomicAdd(&g_fill[d], 1);
    g_colidx[g_rowptr[d] + pos] = s;
}

// ------------- 3xTF32 tensor-core GEMM: g_bufB = A[Arows,128] @ W[128,128] ----
// 128x128 tile/block, BK=32, 256 threads (8 warps), warp tile 32x64 (2x4 wmma).
// Split-precision: x = hi + lo (both tf32); c += al*bh + ah*bl + ah*bh -> ~fp32 accuracy.
#define LDA 40    // 32 + 8 pad  (160B, multiple of 16B)
#define LDB 136   // 128 + 8 pad (544B, multiple of 16B)

__global__ void __launch_bounds__(256) k_gemm(const float* __restrict__ Xext,
                                              const float* __restrict__ W,
                                              int useExt, int Arows) {
    const float* A = useExt ? Xext : g_bufA;
    __shared__ float As[128 * LDA];
    __shared__ float Bs[32 * LDB];

    int tid = threadIdx.x;
    int m0 = blockIdx.x * 128;
    int w  = tid >> 5;
    int wm = w & 3;          // 4 warps along M
    int wn = w >> 2;         // 2 warps along N

    wmma::fragment<wmma::accumulator, 16, 16, 8, float> c[2][4];
#pragma unroll
    for (int i = 0; i < 2; i++)
#pragma unroll
        for (int j = 0; j < 4; j++) wmma::fill_fragment(c[i][j], 0.0f);

    for (int k0 = 0; k0 < HD; k0 += 32) {
        // A tile: 128 x 32 floats = 1024 float4
#pragma unroll
        for (int q = 0; q < 4; q++) {
            int idx = tid + q * 256;
            int row = idx >> 3;
            int cc  = (idx & 7) * 4;
            float4 v = make_float4(0.f, 0.f, 0.f, 0.f);
            if (m0 + row < Arows)
                v = *(const float4*)&A[(size_t)(m0 + row) * HD + k0 + cc];
            *(float4*)&As[row * LDA + cc] = v;
        }
        // B tile: 32 x 128 floats = 1024 float4
#pragma unroll
        for (int q = 0; q < 4; q++) {
            int idx = tid + q * 256;
            int kr = idx >> 5;
            int nn = (idx & 31) * 4;
            *(float4*)&Bs[kr * LDB + nn] = *(const float4*)&W[(k0 + kr) * HD + nn];
        }
        __syncthreads();

#pragma unroll
        for (int kk = 0; kk < 32; kk += 8) {
            wmma::fragment<wmma::matrix_a, 16, 16, 8, wmma::precision::tf32, wmma::row_major> ah[2], al[2];
            wmma::fragment<wmma::matrix_b, 16, 16, 8, wmma::precision::tf32, wmma::row_major> bh[4], bl[4];
#pragma unroll
            for (int i = 0; i < 2; i++) {
                wmma::load_matrix_sync(ah[i], &As[(wm * 32 + i * 16) * LDA + kk], LDA);
#pragma unroll
                for (int t = 0; t < ah[i].num_elements; t++) {
                    float v  = ah[i].x[t];
                    float hi = wmma::__float_to_tf32(v);
                    ah[i].x[t] = hi;
                    al[i].x[t] = wmma::__float_to_tf32(v - hi);
                }
            }
#pragma unroll
            for (int j = 0; j < 4; j++) {
                wmma::load_matrix_sync(bh[j], &Bs[kk * LDB + wn * 64 + j * 16], LDB);
#pragma unroll
                for (int t = 0; t < bh[j].num_elements; t++) {
                    float v  = bh[j].x[t];
                    float hi = wmma::__float_to_tf32(v);
                    bh[j].x[t] = hi;
                    bl[j].x[t] = wmma::__float_to_tf32(v - hi);
                }
            }
#pragma unroll
            for (int i = 0; i < 2; i++)
#pragma unroll
                for (int j = 0; j < 4; j++) {
                    wmma::mma_sync(c[i][j], al[i], bh[j], c[i][j]);
                    wmma::mma_sync(c[i][j], ah[i], bl[j], c[i][j]);
                    wmma::mma_sync(c[i][j], ah[i], bh[j], c[i][j]);
                }
        }
        __syncthreads();
    }

#pragma unroll
    for (int i = 0; i < 2; i++)
#pragma unroll
        for (int j = 0; j < 4; j++) {
            float* dst = &g_bufB[(size_t)(m0 + wm * 32 + i * 16) * HD + wn * 64 + j * 16];
            wmma::store_matrix_sync(dst, c[i][j], HD, wmma::mem_row_major);
        }
}

// ---------------- fused aggregation + bias + ReLU (warp per row, float4) -----
__device__ __forceinline__ float4 f4fma(float s, float4 v, float4 a) {
    a.x += s * v.x; a.y += s * v.y; a.z += s * v.z; a.w += s * v.w;
    return a;
}

__global__ void __launch_bounds__(256) k_agg(const float* __restrict__ bias, int Nrows) {
    int row  = (blockIdx.x * blockDim.x + threadIdx.x) >> 5;
    if (row >= Nrows) return;
    int lane = threadIdx.x & 31;

    const float4* __restrict__ B4 = (const float4*)g_bufB;
    float di  = g_dinv[row];
    float4 acc = make_float4(0.f, 0.f, 0.f, 0.f);
    acc = f4fma(di * di, B4[(size_t)row * 32 + lane], acc);   // self-loop

    int beg = g_rowptr[row], end = g_rowptr[row + 1];
    int e = beg;
    for (; e + 4 <= end; e += 4) {
        int s0 = g_colidx[e],     s1 = g_colidx[e + 1];
        int s2 = g_colidx[e + 2], s3 = g_colidx[e + 3];
        float w0 = g_dinv[s0], w1 = g_dinv[s1], w2 = g_dinv[s2], w3 = g_dinv[s3];
        float4 v0 = B4[(size_t)s0 * 32 + lane];
        float4 v1 = B4[(size_t)s1 * 32 + lane];
        float4 v2 = B4[(size_t)s2 * 32 + lane];
        float4 v3 = B4[(size_t)s3 * 32 + lane];
        acc = f4fma(di * w0, v0, acc);
        acc = f4fma(di * w1, v1, acc);
        acc = f4fma(di * w2, v2, acc);
        acc = f4fma(di * w3, v3, acc);
    }
    for (; e < end; e++) {
        int s = g_colidx[e];
        acc = f4fma(di * g_dinv[s], B4[(size_t)s * 32 + lane], acc);
    }
    float4 b = ((const float4*)bias)[lane];
    acc.x = fmaxf(acc.x + b.x, 0.f);
    acc.y = fmaxf(acc.y + b.y, 0.f);
    acc.z = fmaxf(acc.z + b.z, 0.f);
    acc.w = fmaxf(acc.w + b.w, 0.f);
    ((float4*)g_bufA)[(size_t)row * 32 + lane] = acc;
}

// ---------------- graph boundaries via binary search ----------------
__global__ void k_gptr(const void* batch, int N, int G) {
    int t = blockIdx.x * blockDim.x + threadIdx.x;
    if (t > G) return;
    int is64 = g_is64_batch;
    int lo = 0, hi = N;
    while (lo < hi) {
        int mid = (lo + hi) >> 1;
        if (idx_at(batch, mid, is64) < t) lo = mid + 1; else hi = mid;
    }
    g_gptr[t] = lo;
}

// ---------------- mean pool: block per graph, float4, 4-way node split ------
__global__ void k_pool() {
    int g  = blockIdx.x;
    int t  = threadIdx.x;       // 128
    int f4 = t & 31;            // float4 column
    int ns = t >> 5;            // node sub-lane 0..3
    int beg = g_gptr[g], end = g_gptr[g + 1];

    const float4* __restrict__ A4 = (const float4*)g_bufA;
    float4 s = make_float4(0.f, 0.f, 0.f, 0.f);
    for (int n = beg + ns; n < end; n += 4) {
        float4 v = A4[(size_t)n * 32 + f4];
        s.x += v.x; s.y += v.y; s.z += v.z; s.w += v.w;
    }
    __shared__ float4 sm[128];
    sm[t] = s;
    __syncthreads();
    if (ns == 0) {
        float4 a = sm[f4], b = sm[32 + f4], c = sm[64 + f4], d = sm[96 + f4];
        float inv = 1.f / fmaxf((float)(end - beg), 1.f);
        float4 o;
        o.x = (a.x + b.x + c.x + d.x) * inv;
        o.y = (a.y + b.y + c.y + d.y) * inv;
        o.z = (a.z + b.z + c.z + d.z) * inv;
        o.w = (a.w + b.w + c.w + d.w) * inv;
        ((float4*)g_pool)[g * 32 + f4] = o;
    }
}

// ---------------- head: relu(pool@W1+b1)@W2+b2, log_softmax ----------------
__global__ void k_head(const float* __restrict__ w1, const float* __restrict__ b1,
                       const float* __restrict__ w2, const float* __restrict__ b2,
                       float* __restrict__ out, int C) {
    int g = blockIdx.x, t = threadIdx.x;
    __shared__ float row[HD];
    __shared__ float h1[HD];
    __shared__ float lg[32];
    __shared__ float s_m, s_l;
    row[t] = g_pool[g * HD + t];
    __syncthreads();
    float s = b1[t];
#pragma unroll 8
    for (int k = 0; k < HD; k++) s += row[k] * w1[k * HD + t];
    h1[t] = fmaxf(s, 0.f);
    __syncthreads();
    if (t < C) {
        float s2 = b2[t];
        for (int k = 0; k < HD; k++) s2 += h1[k] * w2[k * C + t];
        lg[t] = s2;
    }
    __syncthreads();
    if (t == 0) {
        float m = -1e30f;
        for (int c = 0; c < C; c++) m = fmaxf(m, lg[c]);
        float se = 0.f;
        for (int c = 0; c < C; c++) se += expf(lg[c] - m);
        s_m = m; s_l = logf(se);
    }
    __syncthreads();
    if (t < C) out[g * C + t] = lg[t] - s_m - s_l;
}

// ---------------- launch ----------------
extern "C" void kernel_launch(void* const* d_in, const int* in_sizes, int n_in,
                              void* d_out, int out_size) {
    const float* x      = (const float*)d_in[0];
    const void*  edge   = d_in[1];
    const void*  batch  = d_in[2];
    const float* w_init = (const float*)d_in[3];
    const float* b_init = (const float*)d_in[4];
    const float* w_conv = (const float*)d_in[5];
    const float* b_conv = (const float*)d_in[6];
    const float* w_h1   = (const float*)d_in[7];
    const float* b_h1   = (const float*)d_in[8];
    const float* w_h2   = (const float*)d_in[9];
    const float* b_h2   = (const float*)d_in[10];

    int H   = in_sizes[4];            // 128
    int N   = in_sizes[0] / H;
    int E   = in_sizes[1] / 2;
    int C   = in_sizes[10];
    int Lm1 = in_sizes[6] / H;
    int G   = out_size / C;

    int tb = 256;
    int nbN = (N + tb - 1) / tb;
    int nbE = (E + tb - 1) / tb;
    int nbS = (N + 1023) / 1024;

    k_detect<<<1, 256>>>(edge, batch, E, N);
    k_zero<<<nbN, tb>>>(N);
    k_hist<<<nbE, tb>>>(edge, E);
    k_scan1<<<nbS, 1024>>>(N);
    k_scan2<<<1, 1024>>>(nbS);
    k_scan3<<<nbS, 1024>>>(N);
    k_dinv<<<nbN, tb>>>(N);
    k_scatter<<<nbE, tb>>>(edge, E);

    int gemmBlocks = (N + 127) / 128;
    int nPad = gemmBlocks * 128;
    int aggBlocks = (N * 32 + 255) / 256;   // warp per row
    // layer 1: x @ w_init -> bufB (guarded reads); aggregate -> bufA
    k_gemm<<<gemmBlocks, 256>>>(x, w_init, 1, N);
    k_agg<<<aggBlocks, 256>>>(b_init, N);
    // layers 2..L (reads from padded g_bufA, zero in pad rows)
    for (int i = 0; i < Lm1; i++) {
        k_gemm<<<gemmBlocks, 256>>>(x, w_conv + (size_t)i * H * H, 0, nPad);
        k_agg<<<aggBlocks, 256>>>(b_conv + (size_t)i * H, N);
    }

    k_gptr<<<1, 256>>>(batch, N, G);
    k_pool<<<G, 128>>>();
    k_head<<<G, 128>>>(w_h1, b_h1, w_h2, b_h2, (float*)d_out, C);
}